// round 3
// baseline (speedup 1.0000x reference)
#include <cuda_runtime.h>
#include <math.h>

// Problem constants
#define BB 64
#define TT 512
#define II 128
#define HH 512
#define OO 64
#define ALPHA 0.1f

// Recurrent kernel config
#define GRID_R 128   // blocks; each owns JT=4 hidden columns
#define JT 4
#define NTH_R 512    // 16 warps; warp w owns batches 4w..4w+3

// Scratch: full hidden history [T][B][H] (64 MB)
__device__ float g_hist[(size_t)TT * BB * HH];
__device__ unsigned g_flags[GRID_R];

__global__ void reset_kernel() {
    int i = threadIdx.x;
    if (i < GRID_R) g_flags[i] = 0u;
}

__device__ __forceinline__ float4 ldcg4(const float* p) {
    return __ldcg(reinterpret_cast<const float4*>(p));
}

// fast tanh via MUFU ex2 path; |err| ~1e-7 rel, no branches
__device__ __forceinline__ float fast_tanh(float x) {
    float e = __expf(2.0f * x);
    return (e - 1.0f) / (e + 1.0f);
}

__global__ void __launch_bounds__(NTH_R, 1) rnn_recurrent(
    const float* __restrict__ x,     // [B][T][I]
    const float* __restrict__ h0,    // [B][H]
    const float* __restrict__ Win,   // [H][I]
    const float* __restrict__ Wrec,  // [H][H]
    const float* __restrict__ bias)  // [H]
{
    const int tid  = threadIdx.x;
    const int warp = tid >> 5;
    const int lane = tid & 31;
    const int j0    = blockIdx.x * JT;  // this block's hidden columns
    const int bbase = warp * 4;         // this warp's batches
    const int k0 = lane * 16;           // this lane's W_rec K-chunk
    const int i0 = lane * 4;            // this lane's W_in I-chunk

    // ---- Preload weights into registers ONCE (reused for all 512 steps) ----
    float4 wr[JT][4];  // W_rec[j0+jj][k0 .. k0+15]
    float4 wi[JT];     // W_in [j0+jj][i0 .. i0+3]
#pragma unroll
    for (int jj = 0; jj < JT; jj++) {
#pragma unroll
        for (int c = 0; c < 4; c++)
            wr[jj][c] = *reinterpret_cast<const float4*>(Wrec + (size_t)(j0 + jj) * HH + k0 + c * 4);
        wi[jj] = *reinterpret_cast<const float4*>(Win + (size_t)(j0 + jj) * II + i0);
    }
    float bj = 0.0f;
    if (lane < 16) bj = bias[j0 + (lane & 3)];
    const int bl_e = lane >> 2, jl_e = lane & 3;  // epilogue ownership (lanes 0..15)

    // ---- Prefetch x for t=0 ----
    float4 xv[4];
#pragma unroll
    for (int bb = 0; bb < 4; bb++)
        xv[bb] = __ldg(reinterpret_cast<const float4*>(
            x + ((size_t)(bbase + bb) * TT + 0) * II + i0));

    for (int t = 0; t < TT; ++t) {
        const float* hprev = (t == 0) ? h0 : (g_hist + (size_t)(t - 1) * BB * HH);

        // issue h_old load early — hidden under the dot product below
        float hold = 0.0f;
        if (lane < 16)
            hold = __ldcg(hprev + (size_t)(bbase + bl_e) * HH + j0 + jl_e);

        float acc[4][JT];
#pragma unroll
        for (int bb = 0; bb < 4; bb++)
#pragma unroll
            for (int jj = 0; jj < JT; jj++) acc[bb][jj] = 0.0f;

#pragma unroll
        for (int bb = 0; bb < 4; bb++) {
            const int bg = bbase + bb;
            const float* hp = hprev + (size_t)bg * HH + k0;
            // recurrent part: h · W_rec^T over this lane's k-chunk
#pragma unroll
            for (int c = 0; c < 4; c++) {
                float4 hv = ldcg4(hp + c * 4);
#pragma unroll
                for (int jj = 0; jj < JT; jj++) {
                    acc[bb][jj] = fmaf(hv.x, wr[jj][c].x, acc[bb][jj]);
                    acc[bb][jj] = fmaf(hv.y, wr[jj][c].y, acc[bb][jj]);
                    acc[bb][jj] = fmaf(hv.z, wr[jj][c].z, acc[bb][jj]);
                    acc[bb][jj] = fmaf(hv.w, wr[jj][c].w, acc[bb][jj]);
                }
            }
            // fused input projection from prefetched registers
#pragma unroll
            for (int jj = 0; jj < JT; jj++) {
                acc[bb][jj] = fmaf(xv[bb].x, wi[jj].x, acc[bb][jj]);
                acc[bb][jj] = fmaf(xv[bb].y, wi[jj].y, acc[bb][jj]);
                acc[bb][jj] = fmaf(xv[bb].z, wi[jj].z, acc[bb][jj]);
                acc[bb][jj] = fmaf(xv[bb].w, wi[jj].w, acc[bb][jj]);
            }
        }

        // Butterfly reduce across the 32 lanes (lanes partition K and I)
#pragma unroll
        for (int off = 16; off >= 1; off >>= 1) {
#pragma unroll
            for (int bb = 0; bb < 4; bb++)
#pragma unroll
                for (int jj = 0; jj < JT; jj++)
                    acc[bb][jj] += __shfl_xor_sync(0xffffffffu, acc[bb][jj], off);
        }

        // Epilogue: lanes 0..15 each own one (batch, j) pair
        if (lane < 16) {
            float pre  = acc[bl_e][jl_e] + bj;
            float hnew = (1.0f - ALPHA) * hold + ALPHA * fast_tanh(pre);
            __stcg(g_hist + (size_t)t * BB * HH +
                       (size_t)(bbase + bl_e) * HH + j0 + jl_e, hnew);
        }

        __syncthreads();
        if (t < TT - 1) {
            // arrive: one flag store per CTA (no atomic contention)
            if (tid == 0) {
                __threadfence();  // block's h stores visible gpu-wide before flag
                __stcg(&g_flags[blockIdx.x], (unsigned)(t + 1));
            }

            // overlap: prefetch x for step t+1 while other CTAs arrive
#pragma unroll
            for (int bb = 0; bb < 4; bb++)
                xv[bb] = __ldg(reinterpret_cast<const float4*>(
                    x + ((size_t)(bbase + bb) * TT + (t + 1)) * II + i0));

            // wait: 128 threads poll 128 distinct flags in parallel
            if (tid < GRID_R) {
                volatile unsigned* f = (volatile unsigned*)&g_flags[tid];
                while (*f < (unsigned)(t + 1)) {}
            }
            __syncthreads();
        }
    }
}

// ---------------- Output projection: out[b][t][o] = hist[t][b] · W_out[o] + b_out[o] ----------------
#define NTH_O 256
#define KC 64

__global__ void __launch_bounds__(NTH_O) rnn_output(
    const float* __restrict__ Wout,  // [O][H]
    const float* __restrict__ bout,  // [O]
    float* __restrict__ out)         // [B][T][O]
{
    const int t = blockIdx.x;
    __shared__ float sH[BB][KC + 4];
    __shared__ float sW[OO][KC + 4];

    const int tid = threadIdx.x;
    const int og = tid & 15;
    const int bg = tid >> 4;

    float acc[4][4];
#pragma unroll
    for (int i = 0; i < 4; i++)
#pragma unroll
        for (int j = 0; j < 4; j++) acc[i][j] = 0.0f;

    const float* hrow = g_hist + (size_t)t * BB * HH;

    for (int kc = 0; kc < HH; kc += KC) {
        for (int idx = tid; idx < BB * (KC / 4); idx += NTH_O) {
            int row = idx / (KC / 4);
            int c4  = idx % (KC / 4);
            float4 v = *reinterpret_cast<const float4*>(hrow + (size_t)row * HH + kc + c4 * 4);
            sH[row][c4 * 4 + 0] = v.x; sH[row][c4 * 4 + 1] = v.y;
            sH[row][c4 * 4 + 2] = v.z; sH[row][c4 * 4 + 3] = v.w;
        }
        for (int idx = tid; idx < OO * (KC / 4); idx += NTH_O) {
            int row = idx / (KC / 4);
            int c4  = idx % (KC / 4);
            float4 v = *reinterpret_cast<const float4*>(Wout + (size_t)row * HH + kc + c4 * 4);
            sW[row][c4 * 4 + 0] = v.x; sW[row][c4 * 4 + 1] = v.y;
            sW[row][c4 * 4 + 2] = v.z; sW[row][c4 * 4 + 3] = v.w;
        }
        __syncthreads();

#pragma unroll
        for (int k = 0; k < KC; k += 4) {
            float4 hv[4], wv[4];
#pragma unroll
            for (int bb = 0; bb < 4; bb++)
                hv[bb] = *reinterpret_cast<const float4*>(&sH[bg * 4 + bb][k]);
#pragma unroll
            for (int oo = 0; oo < 4; oo++)
                wv[oo] = *reinterpret_cast<const float4*>(&sW[og * 4 + oo][k]);
#pragma unroll
            for (int bb = 0; bb < 4; bb++)
#pragma unroll
                for (int oo = 0; oo < 4; oo++) {
                    acc[bb][oo] = fmaf(hv[bb].x, wv[oo].x, acc[bb][oo]);
                    acc[bb][oo] = fmaf(hv[bb].y, wv[oo].y, acc[bb][oo]);
                    acc[bb][oo] = fmaf(hv[bb].z, wv[oo].z, acc[bb][oo]);
                    acc[bb][oo] = fmaf(hv[bb].w, wv[oo].w, acc[bb][oo]);
                }
        }
        __syncthreads();
    }

#pragma unroll
    for (int oo = 0; oo < 4; oo++) {
        float bo = __ldg(bout + og * 4 + oo);
#pragma unroll
        for (int bb = 0; bb < 4; bb++) {
            int b = bg * 4 + bb;
            int o = og * 4 + oo;
            out[(size_t)b * TT * OO + (size_t)t * OO + o] = acc[bb][oo] + bo;
        }
    }
}

__global__ void copy_hfinal(float* __restrict__ dst) {
    int i = blockIdx.x * blockDim.x + threadIdx.x;
    if (i < BB * HH) dst[i] = g_hist[(size_t)(TT - 1) * BB * HH + i];
}

extern "C" void kernel_launch(void* const* d_in, const int* in_sizes, int n_in,
                              void* d_out, int out_size) {
    const float* x    = (const float*)d_in[0];
    const float* h0   = (const float*)d_in[1];
    const float* Win  = (const float*)d_in[2];
    const float* Wrec = (const float*)d_in[3];
    const float* bias = (const float*)d_in[4];
    const float* Wout = (const float*)d_in[5];
    const float* bout = (const float*)d_in[6];
    float* out = (float*)d_out;

    reset_kernel<<<1, 128>>>();
    rnn_recurrent<<<GRID_R, NTH_R>>>(x, h0, Win, Wrec, bias);
    rnn_output<<<TT, NTH_O>>>(Wout, bout, out);
    if (out_size >= BB * TT * OO + BB * HH) {
        copy_hfinal<<<(BB * HH + 255) / 256, 256>>>(out + (size_t)BB * TT * OO);
    }
}

// round 4
// speedup vs baseline: 2.2121x; 2.2121x over previous
#include <cuda_runtime.h>
#include <math.h>

// Problem constants
#define BB 64
#define TT 512
#define II 128
#define HH 512
#define OO 64
#define ALPHA 0.1f

// Recurrent kernel config: 2D tiling
// grid 128 = 16 j-blocks x 8 batch-blocks
// CTA owns 32 j x 8 batches; warp tile 4j x 4b (16 warps = 8 jgrp x 2 bgrp)
#define GRID_R 128
#define NTH_R 512

__device__ float g_hist[(size_t)TT * BB * HH];
__device__ unsigned g_cnt;

__global__ void reset_kernel() { g_cnt = 0u; }

__device__ __forceinline__ float4 ldcg4(const float* p) {
    return __ldcg(reinterpret_cast<const float4*>(p));
}

// fast tanh via MUFU ex2 path; rel err ~1e-7, branch-free
__device__ __forceinline__ float fast_tanh(float x) {
    float e = __expf(2.0f * x);
    return (e - 1.0f) / (e + 1.0f);
}

__global__ void __launch_bounds__(NTH_R, 1) rnn_recurrent(
    const float* __restrict__ x,     // [B][T][I]
    const float* __restrict__ h0,    // [B][H]
    const float* __restrict__ Win,   // [H][I]
    const float* __restrict__ Wrec,  // [H][H]
    const float* __restrict__ bias)  // [H]
{
    __shared__ float sh_h[8][HH];    // this CTA's 8 batches of h_prev (16 KB)
    __shared__ float sh_x[8][II];    // this CTA's 8 batches of x_t     (4 KB)

    const int tid  = threadIdx.x;
    const int warp = tid >> 5;
    const int lane = tid & 31;

    const int jb = blockIdx.x & 15;   // j-block
    const int bblk = blockIdx.x >> 4; // batch-block
    const int j0 = jb * 32;           // CTA's 32 j's
    const int b0 = bblk * 8;          // CTA's 8 batches

    const int jw = warp & 7;          // warp's j-group (4 j)
    const int bw = warp >> 3;         // warp's b-group (4 b)
    const int jbase = jw * 4;         // local j within CTA (0..28)
    const int bbase = bw * 4;         // local b within CTA (0..4)

    // ---- Preload weights into registers ONCE ----
    // lane's k-set: k = c*128 + lane*4 + {0..3}, c = 0..3 (contiguous per lane -> conflict-free LDS)
    float4 wr[4][4];  // wr[jj][c] = Wrec[j0+jbase+jj][c*128 + lane*4 ...]
    float4 wi[4];     // wi[jj]    = Win [j0+jbase+jj][lane*4 ...]
#pragma unroll
    for (int jj = 0; jj < 4; jj++) {
        const float* wrow = Wrec + (size_t)(j0 + jbase + jj) * HH;
#pragma unroll
        for (int c = 0; c < 4; c++)
            wr[jj][c] = *reinterpret_cast<const float4*>(wrow + c * 128 + lane * 4);
        wi[jj] = *reinterpret_cast<const float4*>(Win + (size_t)(j0 + jbase + jj) * II + lane * 4);
    }
    const int bl_e = lane >> 2, jl_e = lane & 3;  // epilogue ownership, lanes 0..15
    float bj = 0.0f;
    if (lane < 16) bj = bias[j0 + jbase + jl_e];

    for (int t = 0; t < TT; ++t) {
        const float* hprev = (t == 0) ? h0 : (g_hist + (size_t)(t - 1) * BB * HH);

        // ---- Stage h_prev[b0..b0+7][:] (16 KB) and x_t[b0..b0+7][:] (4 KB) into SMEM ----
        {
            // h: 1024 float4, 2 per thread
            int idx = tid;
#pragma unroll
            for (int r = 0; r < 2; r++, idx += NTH_R) {
                int row = idx >> 7;          // /128
                int c4  = idx & 127;
                float4 v = ldcg4(hprev + (size_t)(b0 + row) * HH + c4 * 4);
                *reinterpret_cast<float4*>(&sh_h[row][c4 * 4]) = v;
            }
            // x: 256 float4, threads 0..255
            if (tid < 256) {
                int row = tid >> 5;          // /32
                int c4  = tid & 31;
                float4 v = __ldg(reinterpret_cast<const float4*>(
                    x + ((size_t)(b0 + row) * TT + t) * II + c4 * 4));
                *reinterpret_cast<float4*>(&sh_x[row][c4 * 4]) = v;
            }
        }
        __syncthreads();

        // ---- Compute: acc[bb][jj] over this lane's k-set ----
        float acc[4][4];
#pragma unroll
        for (int bb = 0; bb < 4; bb++)
#pragma unroll
            for (int jj = 0; jj < 4; jj++) acc[bb][jj] = 0.0f;

#pragma unroll
        for (int bb = 0; bb < 4; bb++) {
            const int bl = bbase + bb;
            // recurrent part: 4 chunks of 4 k each
#pragma unroll
            for (int c = 0; c < 4; c++) {
                float4 hv = *reinterpret_cast<const float4*>(&sh_h[bl][c * 128 + lane * 4]);
#pragma unroll
                for (int jj = 0; jj < 4; jj++) {
                    acc[bb][jj] = fmaf(hv.x, wr[jj][c].x, acc[bb][jj]);
                    acc[bb][jj] = fmaf(hv.y, wr[jj][c].y, acc[bb][jj]);
                    acc[bb][jj] = fmaf(hv.z, wr[jj][c].z, acc[bb][jj]);
                    acc[bb][jj] = fmaf(hv.w, wr[jj][c].w, acc[bb][jj]);
                }
            }
            // input projection
            float4 xv = *reinterpret_cast<const float4*>(&sh_x[bl][lane * 4]);
#pragma unroll
            for (int jj = 0; jj < 4; jj++) {
                acc[bb][jj] = fmaf(xv.x, wi[jj].x, acc[bb][jj]);
                acc[bb][jj] = fmaf(xv.y, wi[jj].y, acc[bb][jj]);
                acc[bb][jj] = fmaf(xv.z, wi[jj].z, acc[bb][jj]);
                acc[bb][jj] = fmaf(xv.w, wi[jj].w, acc[bb][jj]);
            }
        }

        // ---- Butterfly reduce across lanes (lanes partition k) ----
#pragma unroll
        for (int off = 16; off >= 1; off >>= 1) {
#pragma unroll
            for (int bb = 0; bb < 4; bb++)
#pragma unroll
                for (int jj = 0; jj < 4; jj++)
                    acc[bb][jj] += __shfl_xor_sync(0xffffffffu, acc[bb][jj], off);
        }

        // ---- Epilogue: lanes 0..15 own one (b, j) each ----
        if (lane < 16) {
            const int bl = bbase + bl_e;           // local batch 0..7
            const int jg = j0 + jbase + jl_e;      // global j
            float hold = sh_h[bl][jg];             // h_old from staged tile
            float pre  = acc[bl_e][jl_e] + bj;
            float hnew = (1.0f - ALPHA) * hold + ALPHA * fast_tanh(pre);
            __stcg(g_hist + (size_t)t * BB * HH + (size_t)(b0 + bl) * HH + jg, hnew);
        }

        // ---- Grid barrier (R1-proven: RED arrive + single-thread poll of one address) ----
        __syncthreads();
        if (t < TT - 1) {
            if (tid == 0) {
                __threadfence();
                atomicAdd(&g_cnt, 1u);
                const unsigned target = (unsigned)(t + 1) * GRID_R;
                while (*((volatile unsigned*)&g_cnt) < target) { }
            }
            __syncthreads();
        }
    }
}

// ---------------- Output projection ----------------
#define NTH_O 256
#define KC 64

__global__ void __launch_bounds__(NTH_O) rnn_output(
    const float* __restrict__ Wout,  // [O][H]
    const float* __restrict__ bout,  // [O]
    float* __restrict__ out)         // [B][T][O]
{
    const int t = blockIdx.x;
    __shared__ float sH[BB][KC + 4];
    __shared__ float sW[OO][KC + 4];

    const int tid = threadIdx.x;
    const int og = tid & 15;
    const int bg = tid >> 4;

    float acc[4][4];
#pragma unroll
    for (int i = 0; i < 4; i++)
#pragma unroll
        for (int j = 0; j < 4; j++) acc[i][j] = 0.0f;

    const float* hrow = g_hist + (size_t)t * BB * HH;

    for (int kc = 0; kc < HH; kc += KC) {
        for (int idx = tid; idx < BB * (KC / 4); idx += NTH_O) {
            int row = idx / (KC / 4);
            int c4  = idx % (KC / 4);
            float4 v = *reinterpret_cast<const float4*>(hrow + (size_t)row * HH + kc + c4 * 4);
            sH[row][c4 * 4 + 0] = v.x; sH[row][c4 * 4 + 1] = v.y;
            sH[row][c4 * 4 + 2] = v.z; sH[row][c4 * 4 + 3] = v.w;
        }
        for (int idx = tid; idx < OO * (KC / 4); idx += NTH_O) {
            int row = idx / (KC / 4);
            int c4  = idx % (KC / 4);
            float4 v = *reinterpret_cast<const float4*>(Wout + (size_t)row * HH + kc + c4 * 4);
            sW[row][c4 * 4 + 0] = v.x; sW[row][c4 * 4 + 1] = v.y;
            sW[row][c4 * 4 + 2] = v.z; sW[row][c4 * 4 + 3] = v.w;
        }
        __syncthreads();

#pragma unroll
        for (int k = 0; k < KC; k += 4) {
            float4 hv[4], wv[4];
#pragma unroll
            for (int bb = 0; bb < 4; bb++)
                hv[bb] = *reinterpret_cast<const float4*>(&sH[bg * 4 + bb][k]);
#pragma unroll
            for (int oo = 0; oo < 4; oo++)
                wv[oo] = *reinterpret_cast<const float4*>(&sW[og * 4 + oo][k]);
#pragma unroll
            for (int bb = 0; bb < 4; bb++)
#pragma unroll
                for (int oo = 0; oo < 4; oo++) {
                    acc[bb][oo] = fmaf(hv[bb].x, wv[oo].x, acc[bb][oo]);
                    acc[bb][oo] = fmaf(hv[bb].y, wv[oo].y, acc[bb][oo]);
                    acc[bb][oo] = fmaf(hv[bb].z, wv[oo].z, acc[bb][oo]);
                    acc[bb][oo] = fmaf(hv[bb].w, wv[oo].w, acc[bb][oo]);
                }
        }
        __syncthreads();
    }

#pragma unroll
    for (int oo = 0; oo < 4; oo++) {
        float bo = __ldg(bout + og * 4 + oo);
#pragma unroll
        for (int bb = 0; bb < 4; bb++) {
            int b = bg * 4 + bb;
            int o = og * 4 + oo;
            out[(size_t)b * TT * OO + (size_t)t * OO + o] = acc[bb][oo] + bo;
        }
    }
}

__global__ void copy_hfinal(float* __restrict__ dst) {
    int i = blockIdx.x * blockDim.x + threadIdx.x;
    if (i < BB * HH) dst[i] = g_hist[(size_t)(TT - 1) * BB * HH + i];
}

extern "C" void kernel_launch(void* const* d_in, const int* in_sizes, int n_in,
                              void* d_out, int out_size) {
    const float* x    = (const float*)d_in[0];
    const float* h0   = (const float*)d_in[1];
    const float* Win  = (const float*)d_in[2];
    const float* Wrec = (const float*)d_in[3];
    const float* bias = (const float*)d_in[4];
    const float* Wout = (const float*)d_in[5];
    const float* bout = (const float*)d_in[6];
    float* out = (float*)d_out;

    reset_kernel<<<1, 1>>>();
    rnn_recurrent<<<GRID_R, NTH_R>>>(x, h0, Win, Wrec, bias);
    rnn_output<<<TT, NTH_O>>>(Wout, bout, out);
    if (out_size >= BB * TT * OO + BB * HH) {
        copy_hfinal<<<(BB * HH + 255) / 256, 256>>>(out + (size_t)BB * TT * OO);
    }
}

// round 5
// speedup vs baseline: 2.3179x; 1.0478x over previous
#include <cuda_runtime.h>
#include <math.h>

// Problem constants
#define BB 64
#define TT 512
#define II 128
#define HH 512
#define OO 64
#define ALPHA 0.1f

// Recurrent kernel config: 2D tiling
// grid 128 = 16 j-blocks x 8 batch-blocks
// CTA owns 32 j x 8 batches; warp tile 4j x 4b (16 warps = 8 jgrp x 2 bgrp)
#define GRID_R 128
#define NTH_R 512
#define NJB 16   // j-blocks per batch-block (barrier group size)

__device__ float g_hist[(size_t)TT * BB * HH];
// 8 per-batch-block counters, padded to distinct 128B sectors
__device__ unsigned g_cnt8[8 * 32];

__global__ void reset_kernel() {
    int i = threadIdx.x;
    if (i < 8 * 32) g_cnt8[i] = 0u;
}

__device__ __forceinline__ float4 ldcg4(const float* p) {
    return __ldcg(reinterpret_cast<const float4*>(p));
}

// fast tanh via MUFU ex2 path; rel err ~1e-7, branch-free
__device__ __forceinline__ float fast_tanh(float x) {
    float e = __expf(2.0f * x);
    return (e - 1.0f) / (e + 1.0f);
}

__global__ void __launch_bounds__(NTH_R, 1) rnn_recurrent(
    const float* __restrict__ x,     // [B][T][I]
    const float* __restrict__ h0,    // [B][H]
    const float* __restrict__ Win,   // [H][I]
    const float* __restrict__ Wrec,  // [H][H]
    const float* __restrict__ bias)  // [H]
{
    __shared__ float sh_h[8][HH];    // this CTA's 8 batches of h_prev (16 KB)
    __shared__ float sh_x[8][II];    // this CTA's 8 batches of x_t     (4 KB)

    const int tid  = threadIdx.x;
    const int warp = tid >> 5;
    const int lane = tid & 31;

    const int jb = blockIdx.x & 15;   // j-block
    const int bblk = blockIdx.x >> 4; // batch-block (barrier group)
    const int j0 = jb * 32;           // CTA's 32 j's
    const int b0 = bblk * 8;          // CTA's 8 batches

    const int jw = warp & 7;          // warp's j-group (4 j)
    const int bw = warp >> 3;         // warp's b-group (4 b)
    const int jbase = jw * 4;         // local j within CTA
    const int bbase = bw * 4;         // local b within CTA

    unsigned* my_cnt = &g_cnt8[bblk * 32];

    // ---- Preload weights into registers ONCE ----
    float4 wr[4][4];  // wr[jj][c] = Wrec[j0+jbase+jj][c*128 + lane*4 ...]
    float4 wi[4];     // wi[jj]    = Win [j0+jbase+jj][lane*4 ...]
#pragma unroll
    for (int jj = 0; jj < 4; jj++) {
        const float* wrow = Wrec + (size_t)(j0 + jbase + jj) * HH;
#pragma unroll
        for (int c = 0; c < 4; c++)
            wr[jj][c] = *reinterpret_cast<const float4*>(wrow + c * 128 + lane * 4);
        wi[jj] = *reinterpret_cast<const float4*>(Win + (size_t)(j0 + jbase + jj) * II + lane * 4);
    }
    const int bl_e = lane >> 2, jl_e = lane & 3;  // epilogue ownership, lanes 0..15
    float bj = 0.0f;
    if (lane < 16) bj = bias[j0 + jbase + jl_e];

    // ---- Prefetch x for t=0 into registers (threads 0..255, one float4 each) ----
    const int xrow = tid >> 5;   // /32
    const int xc4  = tid & 31;
    float4 xreg;
    if (tid < 256)
        xreg = __ldg(reinterpret_cast<const float4*>(
            x + ((size_t)(b0 + xrow) * TT + 0) * II + xc4 * 4));

    for (int t = 0; t < TT; ++t) {
        const float* hprev = (t == 0) ? h0 : (g_hist + (size_t)(t - 1) * BB * HH);

        // ---- Stage h_prev (LDG->STS) and x_t (from prefetched regs) ----
        {
            int idx = tid;
#pragma unroll
            for (int r = 0; r < 2; r++, idx += NTH_R) {
                int row = idx >> 7;          // /128
                int c4  = idx & 127;
                float4 v = ldcg4(hprev + (size_t)(b0 + row) * HH + c4 * 4);
                *reinterpret_cast<float4*>(&sh_h[row][c4 * 4]) = v;
            }
            if (tid < 256)
                *reinterpret_cast<float4*>(&sh_x[xrow][xc4 * 4]) = xreg;
        }
        __syncthreads();

        // ---- Compute: acc[bb][jj] over this lane's k-set ----
        float acc[4][4];
#pragma unroll
        for (int bb = 0; bb < 4; bb++)
#pragma unroll
            for (int jj = 0; jj < 4; jj++) acc[bb][jj] = 0.0f;

#pragma unroll
        for (int bb = 0; bb < 4; bb++) {
            const int bl = bbase + bb;
#pragma unroll
            for (int c = 0; c < 4; c++) {
                float4 hv = *reinterpret_cast<const float4*>(&sh_h[bl][c * 128 + lane * 4]);
#pragma unroll
                for (int jj = 0; jj < 4; jj++) {
                    acc[bb][jj] = fmaf(hv.x, wr[jj][c].x, acc[bb][jj]);
                    acc[bb][jj] = fmaf(hv.y, wr[jj][c].y, acc[bb][jj]);
                    acc[bb][jj] = fmaf(hv.z, wr[jj][c].z, acc[bb][jj]);
                    acc[bb][jj] = fmaf(hv.w, wr[jj][c].w, acc[bb][jj]);
                }
            }
            float4 xv = *reinterpret_cast<const float4*>(&sh_x[bl][lane * 4]);
#pragma unroll
            for (int jj = 0; jj < 4; jj++) {
                acc[bb][jj] = fmaf(xv.x, wi[jj].x, acc[bb][jj]);
                acc[bb][jj] = fmaf(xv.y, wi[jj].y, acc[bb][jj]);
                acc[bb][jj] = fmaf(xv.z, wi[jj].z, acc[bb][jj]);
                acc[bb][jj] = fmaf(xv.w, wi[jj].w, acc[bb][jj]);
            }
        }

        // ---- Butterfly reduce across lanes ----
#pragma unroll
        for (int off = 16; off >= 1; off >>= 1) {
#pragma unroll
            for (int bb = 0; bb < 4; bb++)
#pragma unroll
                for (int jj = 0; jj < 4; jj++)
                    acc[bb][jj] += __shfl_xor_sync(0xffffffffu, acc[bb][jj], off);
        }

        // ---- Epilogue: lanes 0..15 own one (b, j) each ----
        if (lane < 16) {
            const int bl = bbase + bl_e;           // local batch 0..7
            const int jg = j0 + jbase + jl_e;      // global j
            float hold = sh_h[bl][jg];
            float pre  = acc[bl_e][jl_e] + bj;
            float hnew = (1.0f - ALPHA) * hold + ALPHA * fast_tanh(pre);
            __stcg(g_hist + (size_t)t * BB * HH + (size_t)(b0 + bl) * HH + jg, hnew);
        }

        // ---- Per-batch-block barrier: 16 arrivals, single-poller ----
        __syncthreads();
        if (t < TT - 1) {
            if (tid == 0) {
                __threadfence();
                atomicAdd(my_cnt, 1u);
            }
            // overlap: prefetch x for t+1 while group-mates arrive
            if (tid < 256)
                xreg = __ldg(reinterpret_cast<const float4*>(
                    x + ((size_t)(b0 + xrow) * TT + (t + 1)) * II + xc4 * 4));
            if (tid == 0) {
                const unsigned target = (unsigned)(t + 1) * NJB;
                while (*((volatile unsigned*)my_cnt) < target) { }
            }
            __syncthreads();
        }
    }
}

// ---------------- Output projection ----------------
#define NTH_O 256
#define KC 64

__global__ void __launch_bounds__(NTH_O) rnn_output(
    const float* __restrict__ Wout,  // [O][H]
    const float* __restrict__ bout,  // [O]
    float* __restrict__ out)         // [B][T][O]
{
    const int t = blockIdx.x;
    __shared__ float sH[BB][KC + 4];
    __shared__ float sW[OO][KC + 4];

    const int tid = threadIdx.x;
    const int og = tid & 15;
    const int bg = tid >> 4;

    float acc[4][4];
#pragma unroll
    for (int i = 0; i < 4; i++)
#pragma unroll
        for (int j = 0; j < 4; j++) acc[i][j] = 0.0f;

    const float* hrow = g_hist + (size_t)t * BB * HH;

    for (int kc = 0; kc < HH; kc += KC) {
        for (int idx = tid; idx < BB * (KC / 4); idx += NTH_O) {
            int row = idx / (KC / 4);
            int c4  = idx % (KC / 4);
            float4 v = *reinterpret_cast<const float4*>(hrow + (size_t)row * HH + kc + c4 * 4);
            sH[row][c4 * 4 + 0] = v.x; sH[row][c4 * 4 + 1] = v.y;
            sH[row][c4 * 4 + 2] = v.z; sH[row][c4 * 4 + 3] = v.w;
        }
        for (int idx = tid; idx < OO * (KC / 4); idx += NTH_O) {
            int row = idx / (KC / 4);
            int c4  = idx % (KC / 4);
            float4 v = *reinterpret_cast<const float4*>(Wout + (size_t)row * HH + kc + c4 * 4);
            sW[row][c4 * 4 + 0] = v.x; sW[row][c4 * 4 + 1] = v.y;
            sW[row][c4 * 4 + 2] = v.z; sW[row][c4 * 4 + 3] = v.w;
        }
        __syncthreads();

#pragma unroll
        for (int k = 0; k < KC; k += 4) {
            float4 hv[4], wv[4];
#pragma unroll
            for (int bb = 0; bb < 4; bb++)
                hv[bb] = *reinterpret_cast<const float4*>(&sH[bg * 4 + bb][k]);
#pragma unroll
            for (int oo = 0; oo < 4; oo++)
                wv[oo] = *reinterpret_cast<const float4*>(&sW[og * 4 + oo][k]);
#pragma unroll
            for (int bb = 0; bb < 4; bb++)
#pragma unroll
                for (int oo = 0; oo < 4; oo++) {
                    acc[bb][oo] = fmaf(hv[bb].x, wv[oo].x, acc[bb][oo]);
                    acc[bb][oo] = fmaf(hv[bb].y, wv[oo].y, acc[bb][oo]);
                    acc[bb][oo] = fmaf(hv[bb].z, wv[oo].z, acc[bb][oo]);
                    acc[bb][oo] = fmaf(hv[bb].w, wv[oo].w, acc[bb][oo]);
                }
        }
        __syncthreads();
    }

#pragma unroll
    for (int oo = 0; oo < 4; oo++) {
        float bo = __ldg(bout + og * 4 + oo);
#pragma unroll
        for (int bb = 0; bb < 4; bb++) {
            int b = bg * 4 + bb;
            int o = og * 4 + oo;
            out[(size_t)b * TT * OO + (size_t)t * OO + o] = acc[bb][oo] + bo;
        }
    }
}

__global__ void copy_hfinal(float* __restrict__ dst) {
    int i = blockIdx.x * blockDim.x + threadIdx.x;
    if (i < BB * HH) dst[i] = g_hist[(size_t)(TT - 1) * BB * HH + i];
}

extern "C" void kernel_launch(void* const* d_in, const int* in_sizes, int n_in,
                              void* d_out, int out_size) {
    const float* x    = (const float*)d_in[0];
    const float* h0   = (const float*)d_in[1];
    const float* Win  = (const float*)d_in[2];
    const float* Wrec = (const float*)d_in[3];
    const float* bias = (const float*)d_in[4];
    const float* Wout = (const float*)d_in[5];
    const float* bout = (const float*)d_in[6];
    float* out = (float*)d_out;

    reset_kernel<<<1, 256>>>();
    rnn_recurrent<<<GRID_R, NTH_R>>>(x, h0, Win, Wrec, bias);
    rnn_output<<<TT, NTH_O>>>(Wout, bout, out);
    if (out_size >= BB * TT * OO + BB * HH) {
        copy_hfinal<<<(BB * HH + 255) / 256, 256>>>(out + (size_t)BB * TT * OO);
    }
}